// round 1
// baseline (speedup 1.0000x reference)
#include <cuda_runtime.h>

// ---------------------------------------------------------------------------
// BidirectionalAttention2: B=64, L1=L2=1024, D=256, fp32.
//
// Decomposed into two flash-attention passes (K == V in both):
//   pass 0: Q=v1, KV=v2, key-logit = v2_mask ? MASK_FILL : q.k ; rows with
//           v1_mask -> 0 output.
//   pass 1: Q=v2, KV=v1, key-logit = v1_mask ? MASK_FILL : q.k ; rows with
//           v2_mask -> 0 output.
// MASK_FILL = -1e-7 (NOT -inf): masked keys still participate in softmax.
//
// Round 0: SIMT fp32 flash kernel. BM=BN=64, D=256 held in registers.
// 256 threads = 16x16; S-phase 4x4 tile/thread, PV-phase 4 rows x 16 cols.
// ---------------------------------------------------------------------------

namespace {
constexpr int kB = 64;
constexpr int kL = 1024;
constexpr int kD = 256;
constexpr int BM = 64;
constexpr int BN = 64;
constexpr int DKP = kD + 4;              // padded KV smem row stride (floats)
constexpr float MASK_FILL = -1e-07f;

constexpr int SQ  = BM * kD;             // Q tile floats
constexpr int SKV = BN * DKP;            // KV tile floats
constexpr int SP  = BM * BN;             // P tile floats
constexpr int SMEM_FLOATS = SQ + SKV + SP + BN;   // + key-mask row
constexpr int SMEM_BYTES  = SMEM_FLOATS * 4;      // 148,736 B
}  // namespace

// mask dtype mode: 0 = 1-byte bool, 1 = int32 {0,1}, 2 = float32 {0,1}
__device__ int g_mask_mode;

__global__ void detect_mask_kernel(const unsigned int* __restrict__ mw) {
    __shared__ int bad_int, bad_float;
    if (threadIdx.x == 0) { bad_int = 0; bad_float = 0; }
    __syncthreads();
    int bi = 0, bf = 0;
    // Inspect (kB*kL)/4 words = 64 KB: in-bounds for every candidate dtype.
    for (int i = threadIdx.x; i < (kB * kL) / 4; i += blockDim.x) {
        unsigned int w = mw[i];
        if (w > 1u) bi = 1;
        if (w != 0u && w != 0x3f800000u) bf = 1;
    }
    if (bi) atomicOr(&bad_int, 1);
    if (bf) atomicOr(&bad_float, 1);
    __syncthreads();
    if (threadIdx.x == 0)
        g_mask_mode = (!bad_int) ? 1 : ((!bad_float) ? 2 : 0);
}

__device__ __forceinline__ bool load_mask(const void* m, int i, int mode) {
    if (mode == 0) return ((const unsigned char*)m)[i] != 0;
    if (mode == 1) return ((const int*)m)[i] != 0;
    return ((const float*)m)[i] != 0.0f;
}

__global__ __launch_bounds__(256, 1)
void fa_kernel(const float* __restrict__ v1, const void* __restrict__ v1m,
               const float* __restrict__ v2, const void* __restrict__ v2m,
               float* __restrict__ out)
{
    extern __shared__ float smem[];
    float* Qs  = smem;                 // [BM][kD]
    float* KVs = smem + SQ;            // [BN][DKP]
    float* Ps  = KVs + SKV;            // [BM][BN]
    float* kms = Ps + SP;              // [BN] key-mask (0/1)

    const int mode = g_mask_mode;
    const int pass = blockIdx.z;
    const int b    = blockIdx.y;
    const int qb   = blockIdx.x;

    const float* Q  = (pass ? v2 : v1) + ((size_t)b * kL + (size_t)qb * BM) * kD;
    const float* KV = (pass ? v1 : v2) + (size_t)b * kL * kD;
    const void*  qm = pass ? v2m : v1m;
    const void*  km = pass ? v1m : v2m;
    const int qoff = b * kL + qb * BM;
    const int koff = b * kL;
    float* O = out + ((size_t)pass * kB * kL + (size_t)b * kL + (size_t)qb * BM) * kD;

    const int tid = threadIdx.x;
    const int tx = tid & 15;           // 0..15
    const int ty = tid >> 4;           // 0..15

    // ---- stage Q tile (coalesced float4) ----
    {
        const float4* src = (const float4*)Q;
        float4* dst = (float4*)Qs;
#pragma unroll
        for (int q = 0; q < (BM * kD / 4) / 256; ++q)
            dst[tid + 256 * q] = src[tid + 256 * q];
    }

    float m_run[4], l_run[4];
    float acc[4][16];                  // rows ty+16i; cols tx*4 + 64g + c
#pragma unroll
    for (int i = 0; i < 4; ++i) {
        m_run[i] = -3.0e38f;
        l_run[i] = 0.0f;
#pragma unroll
        for (int c = 0; c < 16; ++c) acc[i][c] = 0.0f;
    }

    for (int kt = 0; kt < kL / BN; ++kt) {
        __syncthreads();   // prev PV done reading KVs/Ps
        // ---- stage KV tile (serves both K and V) + key masks ----
        {
            const float4* src = (const float4*)(KV + (size_t)kt * BN * kD);
#pragma unroll
            for (int q = 0; q < (BN * kD / 4) / 256; ++q) {
                int idx = tid + 256 * q;
                int row = idx >> 6;          // kD/4 = 64 float4 per row
                int c4  = idx & 63;
                float4 val = src[idx];
                *(float4*)(KVs + row * DKP + (c4 << 2)) = val;
            }
            if (tid < BN)
                kms[tid] = load_mask(km, koff + kt * BN + tid, mode) ? 1.0f : 0.0f;
        }
        __syncthreads();

        // ---- S = Q . K^T  (4x4 per thread, rank-4 updates over d) ----
        float s[4][4];
#pragma unroll
        for (int i = 0; i < 4; ++i)
#pragma unroll
            for (int j = 0; j < 4; ++j) s[i][j] = 0.0f;

#pragma unroll 4
        for (int d = 0; d < kD; d += 4) {
            float4 qv[4], kv[4];
#pragma unroll
            for (int i = 0; i < 4; ++i)
                qv[i] = *(const float4*)(Qs + (ty + 16 * i) * kD + d);
#pragma unroll
            for (int j = 0; j < 4; ++j)
                kv[j] = *(const float4*)(KVs + (tx + 16 * j) * DKP + d);
#pragma unroll
            for (int i = 0; i < 4; ++i)
#pragma unroll
                for (int j = 0; j < 4; ++j) {
                    s[i][j] += qv[i].x * kv[j].x;
                    s[i][j] += qv[i].y * kv[j].y;
                    s[i][j] += qv[i].z * kv[j].z;
                    s[i][j] += qv[i].w * kv[j].w;
                }
        }

        // ---- masking + online softmax (row groups share 16 lanes) ----
        float kmask[4];
#pragma unroll
        for (int j = 0; j < 4; ++j) kmask[j] = kms[tx + 16 * j];

#pragma unroll
        for (int i = 0; i < 4; ++i) {
            float sv[4];
#pragma unroll
            for (int j = 0; j < 4; ++j)
                sv[j] = (kmask[j] != 0.0f) ? MASK_FILL : s[i][j];
            float tmax = fmaxf(fmaxf(sv[0], sv[1]), fmaxf(sv[2], sv[3]));
#pragma unroll
            for (int off = 8; off >= 1; off >>= 1)
                tmax = fmaxf(tmax, __shfl_xor_sync(0xffffffffu, tmax, off));
            float mn = fmaxf(m_run[i], tmax);
            float scale = __expf(m_run[i] - mn);
            float rsum = 0.0f;
#pragma unroll
            for (int j = 0; j < 4; ++j) {
                float p = __expf(sv[j] - mn);
                rsum += p;
                Ps[(ty + 16 * i) * BN + tx + 16 * j] = p;
            }
#pragma unroll
            for (int off = 8; off >= 1; off >>= 1)
                rsum += __shfl_xor_sync(0xffffffffu, rsum, off);
            l_run[i] = l_run[i] * scale + rsum;
            m_run[i] = mn;
#pragma unroll
            for (int c = 0; c < 16; ++c) acc[i][c] *= scale;
        }
        __syncthreads();   // Ps visible

        // ---- O += P . V  (V = same KVs tile) ----
#pragma unroll 2
        for (int n = 0; n < BN; ++n) {
            float pr[4];
#pragma unroll
            for (int i = 0; i < 4; ++i) pr[i] = Ps[(ty + 16 * i) * BN + n];
            float4 vv[4];
#pragma unroll
            for (int g = 0; g < 4; ++g)
                vv[g] = *(const float4*)(KVs + n * DKP + (tx << 2) + 64 * g);
#pragma unroll
            for (int i = 0; i < 4; ++i)
#pragma unroll
                for (int g = 0; g < 4; ++g) {
                    acc[i][4 * g + 0] += pr[i] * vv[g].x;
                    acc[i][4 * g + 1] += pr[i] * vv[g].y;
                    acc[i][4 * g + 2] += pr[i] * vv[g].z;
                    acc[i][4 * g + 3] += pr[i] * vv[g].w;
                }
        }
    }

    // ---- epilogue: normalize, zero masked query rows, store ----
#pragma unroll
    for (int i = 0; i < 4; ++i) {
        int r = ty + 16 * i;
        bool qz = load_mask(qm, qoff + r, mode);
        float inv = qz ? 0.0f : (1.0f / l_run[i]);
#pragma unroll
        for (int g = 0; g < 4; ++g) {
            float4 o;
            o.x = acc[i][4 * g + 0] * inv;
            o.y = acc[i][4 * g + 1] * inv;
            o.z = acc[i][4 * g + 2] * inv;
            o.w = acc[i][4 * g + 3] * inv;
            *(float4*)(O + (size_t)r * kD + (tx << 2) + 64 * g) = o;
        }
    }
}

extern "C" void kernel_launch(void* const* d_in, const int* in_sizes, int n_in,
                              void* d_out, int out_size) {
    (void)in_sizes; (void)n_in; (void)out_size;
    const float* v1  = (const float*)d_in[0];
    const void*  v1m = d_in[1];
    const float* v2  = (const float*)d_in[2];
    const void*  v2m = d_in[3];
    float* out = (float*)d_out;

    cudaFuncSetAttribute(fa_kernel,
                         cudaFuncAttributeMaxDynamicSharedMemorySize, SMEM_BYTES);

    detect_mask_kernel<<<1, 256>>>((const unsigned int*)v1m);
    dim3 grid(kL / BM, kB, 2);
    fa_kernel<<<grid, 256, SMEM_BYTES>>>(v1, v1m, v2, v2m, out);
}